// round 1
// baseline (speedup 1.0000x reference)
#include <cuda_runtime.h>
#include <cstdint>

// Problem shape
#define B_  8
#define H_  512
#define W_  512
#define HW  (H_ * W_)
#define N_PIX (B_ * HW)      // 2,097,152
#define EPS_ 1e-10f

__device__ __forceinline__ float warp_reduce(float v) {
    #pragma unroll
    for (int o = 16; o; o >>= 1) v += __shfl_xor_sync(0xffffffffu, v, o);
    return v;
}

__device__ __forceinline__ void block_reduce_atomic(float v, float* out) {
    __shared__ float s[32];
    v = warp_reduce(v);
    int lane = threadIdx.x & 31;
    int w    = threadIdx.x >> 5;
    if (lane == 0) s[w] = v;
    __syncthreads();
    if (w == 0) {
        int nw = blockDim.x >> 5;
        v = (lane < nw) ? s[lane] : 0.0f;
        v = warp_reduce(v);
        if (lane == 0) atomicAdd(out, v);
    }
}

__global__ void init_out_kernel(float* out) { out[0] = 0.0f; }

// ---------------------------------------------------------------------------
// Fused reconstruction losses: one pass over 12 aligned streams.
//   pre  = |hm0-hm1|, post = |hm1-hm2|
//   loss += 0.25*((r1pf-h1)^2+(r1pb-h1)^2)*roi*(1+pre)
//         + 0.25*((r1nf-h1)^2+(r1nb-h1)^2)*roi*(1+post)
//         + 0.5 *((r0f -h0)^2+(r0b -h0)^2)*roi*(1+pre)
//         + 0.5 *((r2f -h2)^2+(r2b -h2)^2)*roi*(1+post)
// ---------------------------------------------------------------------------
__global__ void rec_loss_kernel(
    const float* __restrict__ roi,
    const float* __restrict__ hm0,  const float* __restrict__ hm1,
    const float* __restrict__ hm2,
    const float* __restrict__ r1pf, const float* __restrict__ r1pb,
    const float* __restrict__ r1nf, const float* __restrict__ r1nb,
    const float* __restrict__ r0f,  const float* __restrict__ r0b,
    const float* __restrict__ r2f,  const float* __restrict__ r2b,
    float* __restrict__ out)
{
    float acc = 0.0f;
    int stride = gridDim.x * blockDim.x;
    for (int i = blockIdx.x * blockDim.x + threadIdx.x; i < N_PIX; i += stride) {
        float h0 = hm0[i], h1 = hm1[i], h2 = hm2[i], m = roi[i];
        float pre  = fabsf(h0 - h1);
        float post = fabsf(h1 - h2);
        float wp = m * (1.0f + pre);
        float wn = m * (1.0f + post);

        float a = r1pf[i] - h1, b = r1pb[i] - h1;
        float c = r1nf[i] - h1, d = r1nb[i] - h1;
        float e = r0f[i]  - h0, f = r0b[i]  - h0;
        float g = r2f[i]  - h2, k = r2b[i]  - h2;

        acc += 0.25f * ((a*a + b*b) * wp + (c*c + d*d) * wn)
             + 0.50f * ((e*e + f*f) * wp + (g*g + k*k) * wn);
    }
    block_reduce_atomic(acc, out);
}

// ---------------------------------------------------------------------------
// Flow consistency: for each pixel, loop over 9 channels x 2 flow pairs.
// Channel i: dy = {1,1,1,0,0,0,-1,-1,-1}[i], dx = {1,0,-1}[i%3]
//   contributes roi[y,x] * (clip(flow[i,y,x]) - clip(inv[8-i,y-dy,x-dx]))^2
// valid iff (y-dy, x-dx) in bounds. Total scaled by 1/9 at accumulation.
// ---------------------------------------------------------------------------
__global__ void flow_cons_kernel(
    const float* __restrict__ roi,
    const float* __restrict__ f01f, const float* __restrict__ f10b,
    const float* __restrict__ f12f, const float* __restrict__ f21b,
    float* __restrict__ out)
{
    float acc = 0.0f;
    int stride = gridDim.x * blockDim.x;
    for (int pid = blockIdx.x * blockDim.x + threadIdx.x; pid < N_PIX; pid += stride) {
        int b   = pid >> 18;           // / HW (HW = 2^18)
        int rem = pid & (HW - 1);
        int y   = rem >> 9;            // / W_
        int x   = rem & (W_ - 1);

        float m = roi[pid];
        long base = (long)b * 9 * HW + (long)y * W_ + x;

        const float* fw[2]  = { f01f, f12f };
        const float* inv[2] = { f10b, f21b };

        float pix = 0.0f;
        #pragma unroll
        for (int p = 0; p < 2; ++p) {
            const float* F = fw[p];
            const float* I = inv[p];
            float s = 0.0f;
            #pragma unroll
            for (int i = 0; i < 9; ++i) {
                const int dy = (i < 3) ? 1 : (i < 6) ? 0 : -1;
                const int mm = i % 3;
                const int dx = (mm == 0) ? 1 : (mm == 1) ? 0 : -1;
                int yy = y - dy, xx = x - dx;
                if ((unsigned)yy < (unsigned)H_ && (unsigned)xx < (unsigned)W_) {
                    float a = F[base + (long)i * HW];
                    float v = I[(long)b * 9 * HW + (long)(8 - i) * HW
                                + (long)yy * W_ + xx];
                    a = fminf(fmaxf(a, EPS_), 1.0f - EPS_);
                    v = fminf(fmaxf(v, EPS_), 1.0f - EPS_);
                    float d = a - v;
                    s += d * d;
                }
            }
            pix += s;
        }
        acc += m * pix;
    }
    block_reduce_atomic(acc * (1.0f / 9.0f), out);
}

extern "C" void kernel_launch(void* const* d_in, const int* in_sizes, int n_in,
                              void* d_out, int out_size)
{
    // metadata order:
    // 0 roi_mask, 1 boundary_mask (UNUSED), 2 hm_0, 3 hm_1, 4 hm_2,
    // 5 rec_1pf, 6 rec_1pb, 7 rec_1nf, 8 rec_1nb,
    // 9 rec_0f, 10 rec_0b, 11 rec_2f, 12 rec_2b,
    // 13 flow_0_1f, 14 flow_1_0b, 15 flow_1_2f, 16 flow_2_1b
    const float* roi  = (const float*)d_in[0];
    const float* hm0  = (const float*)d_in[2];
    const float* hm1  = (const float*)d_in[3];
    const float* hm2  = (const float*)d_in[4];
    const float* r1pf = (const float*)d_in[5];
    const float* r1pb = (const float*)d_in[6];
    const float* r1nf = (const float*)d_in[7];
    const float* r1nb = (const float*)d_in[8];
    const float* r0f  = (const float*)d_in[9];
    const float* r0b  = (const float*)d_in[10];
    const float* r2f  = (const float*)d_in[11];
    const float* r2b  = (const float*)d_in[12];
    const float* f01f = (const float*)d_in[13];
    const float* f10b = (const float*)d_in[14];
    const float* f12f = (const float*)d_in[15];
    const float* f21b = (const float*)d_in[16];

    float* out = (float*)d_out;

    init_out_kernel<<<1, 1>>>(out);

    const int threads = 256;
    int rec_blocks  = 4096;   // grid-stride, ~2 elems/thread
    int flow_blocks = 8192;   // 1 pixel/thread

    rec_loss_kernel<<<rec_blocks, threads>>>(
        roi, hm0, hm1, hm2, r1pf, r1pb, r1nf, r1nb, r0f, r0b, r2f, r2b, out);

    flow_cons_kernel<<<flow_blocks, threads>>>(
        roi, f01f, f10b, f12f, f21b, out);
}

// round 3
// speedup vs baseline: 1.0596x; 1.0596x over previous
#include <cuda_runtime.h>
#include <cstdint>

#define B_  8
#define H_  512
#define W_  512
#define HW  (H_ * W_)
#define N_PIX (B_ * HW)          // 2,097,152
#define NV    (N_PIX / 4)        // 524,288 float4 chunks
#define EPS_  1e-10f

#define THREADS 256
#define BLOCKS  (NV / THREADS)   // 2048 — exactly one chunk per thread per phase

// Device-global accumulator state (zero at module load; reset by last block
// each launch so the kernel is deterministic across graph replays).
__device__ float        g_acc;
__device__ unsigned int g_count;

__device__ __forceinline__ float clipf(float v) {
    return fminf(fmaxf(v, EPS_), 1.0f - EPS_);
}

__device__ __forceinline__ float warp_reduce(float v) {
    #pragma unroll
    for (int o = 16; o; o >>= 1) v += __shfl_xor_sync(0xffffffffu, v, o);
    return v;
}

__global__ __launch_bounds__(THREADS)
void fused_loss_kernel(
    const float* __restrict__ roi,
    const float* __restrict__ hm0,  const float* __restrict__ hm1,
    const float* __restrict__ hm2,
    const float* __restrict__ r1pf, const float* __restrict__ r1pb,
    const float* __restrict__ r1nf, const float* __restrict__ r1nb,
    const float* __restrict__ r0f,  const float* __restrict__ r0b,
    const float* __restrict__ r2f,  const float* __restrict__ r2b,
    const float* __restrict__ f01f, const float* __restrict__ f10b,
    const float* __restrict__ f12f, const float* __restrict__ f21b,
    float* __restrict__ out)
{
    const int tid = blockIdx.x * THREADS + threadIdx.x;   // 0 .. NV-1
    float acc = 0.0f;

    // ---------------- Phase A: reconstruction losses (float4, all aligned) --
    {
        const int i = tid;
        float4 m4  = ((const float4*)roi )[i];
        float4 h04 = ((const float4*)hm0 )[i];
        float4 h14 = ((const float4*)hm1 )[i];
        float4 h24 = ((const float4*)hm2 )[i];
        float4 a4  = ((const float4*)r1pf)[i];
        float4 b4  = ((const float4*)r1pb)[i];
        float4 c4  = ((const float4*)r1nf)[i];
        float4 d4  = ((const float4*)r1nb)[i];
        float4 e4  = ((const float4*)r0f )[i];
        float4 f4  = ((const float4*)r0b )[i];
        float4 g4  = ((const float4*)r2f )[i];
        float4 k4  = ((const float4*)r2b )[i];

        const float* m  = &m4.x;
        const float* h0 = &h04.x; const float* h1 = &h14.x; const float* h2 = &h24.x;
        const float* pa = &a4.x;  const float* pb = &b4.x;
        const float* pc = &c4.x;  const float* pd = &d4.x;
        const float* pe = &e4.x;  const float* pf = &f4.x;
        const float* pg = &g4.x;  const float* pk = &k4.x;

        #pragma unroll
        for (int j = 0; j < 4; ++j) {
            float pre  = fabsf(h0[j] - h1[j]);
            float post = fabsf(h1[j] - h2[j]);
            float wp = m[j] * (1.0f + pre);
            float wn = m[j] * (1.0f + post);

            float a = pa[j] - h1[j], b = pb[j] - h1[j];
            float c = pc[j] - h1[j], d = pd[j] - h1[j];
            float e = pe[j] - h0[j], f = pf[j] - h0[j];
            float g = pg[j] - h2[j], k = pk[j] - h2[j];

            acc += 0.25f * ((a*a + b*b) * wp + (c*c + d*d) * wn)
                 + 0.50f * ((e*e + f*f) * wp + (g*g + k*k) * wn);
        }
    }

    // ---------------- Phase B: flow consistency (4-wide pixel chunks) -------
    {
        const int c   = tid;
        const int pid = c * 4;
        const int b   = pid >> 18;            // / HW
        const int rem = pid & (HW - 1);
        const int y   = rem >> 9;             // / W
        const int x0  = rem & (W_ - 1);       // multiple of 4

        float4 m4 = ((const float4*)roi)[c];
        const float* mj = &m4.x;

        const size_t base_b = (size_t)b * 9 * HW;
        const size_t rowF   = base_b + (size_t)y * W_ + x0;

        float s[4] = {0.f, 0.f, 0.f, 0.f};

        const float* FW[2]  = { f01f, f12f };
        const float* IV[2]  = { f10b, f21b };

        #pragma unroll
        for (int p = 0; p < 2; ++p) {
            const float* F = FW[p];
            const float* I = IV[p];
            #pragma unroll
            for (int i = 0; i < 9; ++i) {
                const int dy = (i < 3) ? 1 : (i < 6) ? 0 : -1;
                const int mm = i % 3;
                const int dx = (mm == 0) ? 1 : (mm == 1) ? 0 : -1;

                const int yy = y - dy;
                if ((unsigned)yy >= (unsigned)H_) continue;

                float4 fv = *(const float4*)(F + rowF + (size_t)i * HW);
                const float* fj = &fv.x;
                const float* Irow = I + base_b + (size_t)(8 - i) * HW + (size_t)yy * W_;

                if (dx == 0) {
                    float4 iv = *(const float4*)(Irow + x0);
                    const float* ij = &iv.x;
                    #pragma unroll
                    for (int j = 0; j < 4; ++j) {
                        float d = clipf(fj[j]) - clipf(ij[j]);
                        s[j] += d * d;
                    }
                } else {
                    #pragma unroll
                    for (int j = 0; j < 4; ++j) {
                        const int xx = x0 + j - dx;
                        if ((unsigned)xx < (unsigned)W_) {
                            float d = clipf(fj[j]) - clipf(Irow[xx]);
                            s[j] += d * d;
                        }
                    }
                }
            }
        }

        acc += (1.0f / 9.0f) * (mj[0]*s[0] + mj[1]*s[1] + mj[2]*s[2] + mj[3]*s[3]);
    }

    // ---------------- Block reduction + last-block finalize -----------------
    __shared__ float smem[THREADS / 32];
    float v = warp_reduce(acc);
    const int lane = threadIdx.x & 31;
    const int w    = threadIdx.x >> 5;
    if (lane == 0) smem[w] = v;
    __syncthreads();
    if (w == 0) {
        v = (lane < THREADS / 32) ? smem[lane] : 0.0f;
        v = warp_reduce(v);
        if (lane == 0) {
            atomicAdd(&g_acc, v);
            __threadfence();
            unsigned ticket = atomicAdd(&g_count, 1u);
            if (ticket == gridDim.x - 1) {
                // All blocks' g_acc adds are visible (fence-before-ticket).
                float total = atomicExch(&g_acc, 0.0f);   // read + reset
                out[0] = total;
                atomicExch(&g_count, 0u);                 // reset for next replay
            }
        }
    }
}

extern "C" void kernel_launch(void* const* d_in, const int* in_sizes, int n_in,
                              void* d_out, int out_size)
{
    const float* roi  = (const float*)d_in[0];
    // d_in[1] = boundary_mask (unused by the reference)
    const float* hm0  = (const float*)d_in[2];
    const float* hm1  = (const float*)d_in[3];
    const float* hm2  = (const float*)d_in[4];
    const float* r1pf = (const float*)d_in[5];
    const float* r1pb = (const float*)d_in[6];
    const float* r1nf = (const float*)d_in[7];
    const float* r1nb = (const float*)d_in[8];
    const float* r0f  = (const float*)d_in[9];
    const float* r0b  = (const float*)d_in[10];
    const float* r2f  = (const float*)d_in[11];
    const float* r2b  = (const float*)d_in[12];
    const float* f01f = (const float*)d_in[13];
    const float* f10b = (const float*)d_in[14];
    const float* f12f = (const float*)d_in[15];
    const float* f21b = (const float*)d_in[16];

    fused_loss_kernel<<<BLOCKS, THREADS>>>(
        roi, hm0, hm1, hm2,
        r1pf, r1pb, r1nf, r1nb, r0f, r0b, r2f, r2b,
        f01f, f10b, f12f, f21b,
        (float*)d_out);
}